// round 8
// baseline (speedup 1.0000x reference)
#include <cuda_runtime.h>
#include <cstdint>

// Problem-size constants (validated against in_sizes at launch; sized for this dataset)
#define MAX_N      150000
#define EMBD       64
#define ALLW       256   // 4 * EMB concatenated width

// -------- scratch (device globals: no allocations allowed) ----------------
__device__ float g_side[(size_t)MAX_N * EMBD];   // 38.4 MB
__device__ float g_ego [(size_t)MAX_N * EMBD];   // 38.4 MB
__device__ float g_alle[(size_t)MAX_N * ALLW];   // 153.6 MB

// ---------------------------------------------------------------------------
// init: ego = concat(user_emb,item_emb); all_e[:,0:64] = ego; side = 0
// one thread per float4 chunk of a row (16 chunks/row)
// ---------------------------------------------------------------------------
__global__ void k_init(const float4* __restrict__ ue, const float4* __restrict__ ie,
                       int n_user, int N)
{
    size_t t = (size_t)blockIdx.x * blockDim.x + threadIdx.x;
    size_t total = (size_t)N * 16;
    if (t >= total) return;
    int row = (int)(t >> 4);
    int c   = (int)(t & 15);
    float4 v = (row < n_user) ? ue[(size_t)row * 16 + c]
                              : ie[(size_t)(row - n_user) * 16 + c];
    reinterpret_cast<float4*>(g_ego )[t] = v;
    reinterpret_cast<float4*>(g_side)[t] = make_float4(0.f, 0.f, 0.f, 0.f);
    reinterpret_cast<float4*>(g_alle)[(size_t)row * 64 + c] = v;  // cols 0..63
}

// ---------------------------------------------------------------------------
// scatter: side[dst] += ego[src] * w   (16 threads / edge, float4 vector red)
// ---------------------------------------------------------------------------
__global__ void k_scatter(const int* __restrict__ src, const int* __restrict__ dst,
                          const float* __restrict__ w, int nE)
{
    size_t tid = (size_t)blockIdx.x * blockDim.x + threadIdx.x;
    int e = (int)(tid >> 4);
    int c = (int)(tid & 15);
    if (e >= nE) return;
    int s  = __ldg(&src[e]);
    int d  = __ldg(&dst[e]);
    float wt = __ldg(&w[e]);
    const float4* ep =
        reinterpret_cast<const float4*>(&g_ego[(size_t)s * EMBD + c * 4]);
    float4 v = __ldg(ep);
    v.x *= wt; v.y *= wt; v.z *= wt; v.w *= wt;
    unsigned long long gp =
        __cvta_generic_to_global(&g_side[(size_t)d * EMBD + c * 4]);
    asm volatile("red.global.add.v4.f32 [%0], {%1,%2,%3,%4};"
                 :: "l"(gp), "f"(v.x), "f"(v.y), "f"(v.z), "f"(v.w) : "memory");
}

// ---------------------------------------------------------------------------
// transform: fused dual-GEMM + bias + leaky_relu + row-norm.
//   sum_e = side @ Wgc + bgc ; bi_e = (ego*side) @ Wbi + bbi
//   ego   = leaky_relu(sum_e + bi_e, 0.2)   (in-place, unnormalized)
//   all_e[:, 64*(layer+1) : +64] = ego / max(||ego||, 1e-12)
//   also re-zeroes side for the next layer (saves a memset launch).
// One node per thread; 64 fp32 accumulators; weights broadcast from smem.
// ---------------------------------------------------------------------------
__global__ void __launch_bounds__(128)
k_transform(const float* __restrict__ Wgc, const float* __restrict__ bgc,
            const float* __restrict__ Wbi, const float* __restrict__ bbi,
            int N, int out_col)
{
    __shared__ float sWgc[EMBD * EMBD];
    __shared__ float sWbi[EMBD * EMBD];
    __shared__ float sB[EMBD];

    for (int t = threadIdx.x; t < EMBD * EMBD; t += blockDim.x) {
        sWgc[t] = Wgc[t];
        sWbi[t] = Wbi[t];
    }
    if (threadIdx.x < EMBD) sB[threadIdx.x] = bgc[threadIdx.x] + bbi[threadIdx.x];
    __syncthreads();

    int n = blockIdx.x * blockDim.x + threadIdx.x;
    if (n >= N) return;

    float* sp = &g_side[(size_t)n * EMBD];
    float* ep = &g_ego [(size_t)n * EMBD];

    float acc[EMBD];
    #pragma unroll
    for (int j = 0; j < EMBD; j++) acc[j] = sB[j];

    #pragma unroll 4
    for (int i = 0; i < EMBD; i++) {
        float s = sp[i];
        float p = s * ep[i];
        const float4* wg = reinterpret_cast<const float4*>(&sWgc[i * EMBD]);
        const float4* wb = reinterpret_cast<const float4*>(&sWbi[i * EMBD]);
        #pragma unroll
        for (int j4 = 0; j4 < 16; j4++) {
            float4 a = wg[j4];
            float4 b = wb[j4];
            acc[j4 * 4 + 0] += s * a.x + p * b.x;
            acc[j4 * 4 + 1] += s * a.y + p * b.y;
            acc[j4 * 4 + 2] += s * a.z + p * b.z;
            acc[j4 * 4 + 3] += s * a.w + p * b.w;
        }
    }

    float sumsq = 0.f;
    #pragma unroll
    for (int j = 0; j < EMBD; j++) {
        float v = acc[j];
        v = (v >= 0.f) ? v : 0.2f * v;
        acc[j] = v;
        sumsq += v * v;
    }
    float inv = 1.0f / fmaxf(sqrtf(sumsq), 1e-12f);

    float* ap = &g_alle[(size_t)n * ALLW + out_col];
    #pragma unroll
    for (int j4 = 0; j4 < 16; j4++) {
        float4 v = make_float4(acc[j4*4+0], acc[j4*4+1], acc[j4*4+2], acc[j4*4+3]);
        *reinterpret_cast<float4*>(&ep[j4 * 4]) = v;                    // ego (unnormalized)
        v.x *= inv; v.y *= inv; v.z *= inv; v.w *= inv;
        *reinterpret_cast<float4*>(&ap[j4 * 4]) = v;                    // normalized slice
        *reinterpret_cast<float4*>(&sp[j4 * 4]) = make_float4(0,0,0,0); // side := 0
    }
}

// ---------------------------------------------------------------------------
// final gather: out = [all_e[users], all_e[n_user+pos], all_e[n_user+neg]]
// Index arrays may be int32 or int64 (JAX x64 ambiguity) -> detect on device:
// for int64 little-endian values < 2^31, every odd 32-bit word is 0.
// ---------------------------------------------------------------------------
__device__ __forceinline__ int detect_is64(const int* w, int count)
{
    int n = (count < 64) ? count : 64;
    int f = 0;
    for (int k = 1; k < 2 * n; k += 2) f |= w[k];
    return (f == 0) ? 1 : 0;
}

__global__ void k_gather(const void* __restrict__ users, const void* __restrict__ pos,
                         const void* __restrict__ neg, float* __restrict__ out,
                         int n_user, int batch)
{
    __shared__ int sIs64[3];
    if (threadIdx.x < 3) {
        const void* a = (threadIdx.x == 0) ? users : (threadIdx.x == 1) ? pos : neg;
        sIs64[threadIdx.x] = detect_is64(reinterpret_cast<const int*>(a), batch);
    }
    __syncthreads();

    int row = blockIdx.x * 4 + (threadIdx.x >> 6);   // 4 rows / 256-thread block
    int c   = threadIdx.x & 63;
    if (row >= 3 * batch) return;
    int grp = row / batch;
    int idx = row - grp * batch;
    const void* a = (grp == 0) ? users : (grp == 1) ? pos : neg;
    long long node;
    if (sIs64[grp]) node = reinterpret_cast<const long long*>(a)[idx];
    else            node = (long long)reinterpret_cast<const int*>(a)[idx];
    if (grp > 0) node += n_user;

    float4 v = *reinterpret_cast<const float4*>(&g_alle[(size_t)node * ALLW + c * 4]);
    *reinterpret_cast<float4*>(&out[(size_t)row * ALLW + c * 4]) = v;
}

// ---------------------------------------------------------------------------
extern "C" void kernel_launch(void* const* d_in, const int* in_sizes, int n_in,
                              void* d_out, int out_size)
{
    const float* user_emb = (const float*)d_in[0];
    const float* item_emb = (const float*)d_in[1];
    const float* W_gc     = (const float*)d_in[2];
    const float* b_gc     = (const float*)d_in[3];
    const float* W_bi     = (const float*)d_in[4];
    const float* b_bi     = (const float*)d_in[5];
    const float* edge_w   = (const float*)d_in[6];
    const int*   edge_src = (const int*)  d_in[7];
    const int*   edge_dst = (const int*)  d_in[8];
    const void*  users    = d_in[9];
    const void*  pos      = d_in[10];
    const void*  neg      = d_in[11];

    int n_user = in_sizes[0] / EMBD;
    int n_item = in_sizes[1] / EMBD;
    int N      = n_user + n_item;
    int layers = in_sizes[2] / (EMBD * EMBD);
    int nE     = in_sizes[6];
    int batch  = in_sizes[9];

    // init
    {
        size_t total = (size_t)N * 16;
        int grid = (int)((total + 255) / 256);
        k_init<<<grid, 256>>>((const float4*)user_emb, (const float4*)item_emb,
                              n_user, N);
    }

    // propagation layers
    for (int k = 0; k < layers; k++) {
        {
            size_t threads = (size_t)nE * 16;
            int grid = (int)((threads + 255) / 256);
            k_scatter<<<grid, 256>>>(edge_src, edge_dst, edge_w, nE);
        }
        {
            int grid = (N + 127) / 128;
            k_transform<<<grid, 128>>>(W_gc + (size_t)k * EMBD * EMBD,
                                       b_gc + (size_t)k * EMBD,
                                       W_bi + (size_t)k * EMBD * EMBD,
                                       b_bi + (size_t)k * EMBD,
                                       N, EMBD * (k + 1));
        }
    }

    // final gather
    {
        int rows = 3 * batch;
        int grid = (rows + 3) / 4;
        k_gather<<<grid, 256>>>(users, pos, neg, (float*)d_out, n_user, batch);
    }
}

// round 9
// speedup vs baseline: 1.8296x; 1.8296x over previous
#include <cuda_runtime.h>
#include <cstdint>

// Problem-size constants (sized for this dataset)
#define MAX_N      150016
#define MAX_E      4194304
#define EMBD       64
#define ALLW       256   // 4 * EMB concatenated width

// -------- scratch (device globals: no allocations allowed) ----------------
__device__ float g_side[(size_t)MAX_N * EMBD];     // 38.4 MB
__device__ float g_ego [(size_t)MAX_N * EMBD];     // 38.4 MB
__device__ float g_alle[(size_t)MAX_N * ALLW];     // 153.6 MB
__device__ int   g_deg [MAX_N];
__device__ int   g_row [MAX_N + 1];
__device__ int   g_cur [MAX_N];
__device__ int   g_partial[256];
__device__ int   g_poff  [256];
__device__ int2  g_edge[MAX_E];                    // (src, w-bits) 32 MB

// ---------------------------------------------------------------------------
// init: ego = concat(user_emb,item_emb); all_e[:,0:64] = ego; deg = 0
// ---------------------------------------------------------------------------
__global__ void k_init(const float4* __restrict__ ue, const float4* __restrict__ ie,
                       int n_user, int N)
{
    size_t t = (size_t)blockIdx.x * blockDim.x + threadIdx.x;
    size_t total = (size_t)N * 16;
    if (t >= total) return;
    int row = (int)(t >> 4);
    int c   = (int)(t & 15);
    float4 v = (row < n_user) ? ue[(size_t)row * 16 + c]
                              : ie[(size_t)(row - n_user) * 16 + c];
    reinterpret_cast<float4*>(g_ego )[t] = v;
    reinterpret_cast<float4*>(g_alle)[(size_t)row * 64 + c] = v;  // cols 0..63
    if (c == 0) g_deg[row] = 0;
}

// ---------------------------------------------------------------------------
// CSR build: histogram -> block sums -> scan partials -> write offsets -> fill
// ---------------------------------------------------------------------------
__global__ void k_hist(const int* __restrict__ dst, int nE)
{
    int e = blockIdx.x * blockDim.x + threadIdx.x;
    if (e < nE) atomicAdd(&g_deg[dst[e]], 1);
}

// block of 256 threads covers 1024 elements; writes per-block sum
__global__ void k_scan_blocks(int N)
{
    __shared__ int s[256];
    int tid  = threadIdx.x;
    int base = blockIdx.x * 1024 + tid * 4;
    int ts = 0;
    #pragma unroll
    for (int k = 0; k < 4; k++)
        if (base + k < N) ts += g_deg[base + k];
    s[tid] = ts;
    __syncthreads();
    for (int off = 128; off > 0; off >>= 1) {
        if (tid < off) s[tid] += s[tid + off];
        __syncthreads();
    }
    if (tid == 0) g_partial[blockIdx.x] = s[0];
}

// single block: exclusive scan of nblk (<=256) partials; also row[N] = nE
__global__ void k_scan_partials(int nblk, int nE, int N)
{
    __shared__ int s[256];
    int tid = threadIdx.x;
    int v = (tid < nblk) ? g_partial[tid] : 0;
    s[tid] = v;
    __syncthreads();
    for (int off = 1; off < 256; off <<= 1) {
        int t = (tid >= off) ? s[tid - off] : 0;
        __syncthreads();
        s[tid] += t;
        __syncthreads();
    }
    g_poff[tid] = s[tid] - v;   // exclusive
    if (tid == 0) g_row[N] = nE;
}

__global__ void k_scan_write(int N)
{
    __shared__ int s[256];
    int tid  = threadIdx.x;
    int base = blockIdx.x * 1024 + tid * 4;
    int v[4]; int ts = 0;
    #pragma unroll
    for (int k = 0; k < 4; k++) {
        v[k] = (base + k < N) ? g_deg[base + k] : 0;
        ts += v[k];
    }
    s[tid] = ts;
    __syncthreads();
    for (int off = 1; off < 256; off <<= 1) {
        int t = (tid >= off) ? s[tid - off] : 0;
        __syncthreads();
        s[tid] += t;
        __syncthreads();
    }
    int excl = s[tid] - ts + g_poff[blockIdx.x];
    #pragma unroll
    for (int k = 0; k < 4; k++) {
        if (base + k < N) {
            g_row[base + k] = excl;
            g_cur[base + k] = excl;
            excl += v[k];
        }
    }
}

__global__ void k_fill(const int* __restrict__ src, const int* __restrict__ dst,
                       const float* __restrict__ w, int nE)
{
    int e = blockIdx.x * blockDim.x + threadIdx.x;
    if (e >= nE) return;
    int d   = dst[e];
    int pos = atomicAdd(&g_cur[d], 1);
    g_edge[pos] = make_int2(src[e], __float_as_int(w[e]));
}

// ---------------------------------------------------------------------------
// aggregate (replaces atomic scatter): side[n] = sum_{e in CSR row n} w_e * ego[src_e]
// 16 threads per node, each owns one float4 chunk. No atomics.
// ---------------------------------------------------------------------------
__global__ void __launch_bounds__(256)
k_aggregate(int N)
{
    size_t t = (size_t)blockIdx.x * blockDim.x + threadIdx.x;
    int node = (int)(t >> 4);
    int c    = (int)(t & 15);
    if (node >= N) return;
    int beg = g_row[node];
    int end = g_row[node + 1];
    float4 acc = make_float4(0.f, 0.f, 0.f, 0.f);
    #pragma unroll 4
    for (int e = beg; e < end; e++) {
        int2  sw = g_edge[e];
        float w  = __int_as_float(sw.y);
        float4 v = __ldg(reinterpret_cast<const float4*>(
                        &g_ego[(size_t)sw.x * EMBD + c * 4]));
        acc.x += w * v.x; acc.y += w * v.y;
        acc.z += w * v.z; acc.w += w * v.w;
    }
    *reinterpret_cast<float4*>(&g_side[(size_t)node * EMBD + c * 4]) = acc;
}

// ---------------------------------------------------------------------------
// transform: fused dual-GEMM + bias + leaky_relu + row-norm, packed f32x2 FMA.
//   sum_e = side @ Wgc + bgc ; bi_e = (ego*side) @ Wbi + bbi
//   ego   = leaky_relu(sum_e + bi_e, 0.2)   (in-place, unnormalized)
//   all_e[:, out_col : out_col+64] = ego / max(||ego||, 1e-12)
// ---------------------------------------------------------------------------
#define FMA2(d, a, b) asm("fma.rn.f32x2 %0, %1, %2, %0;" : "+l"(d) : "l"(a), "l"(b))

__device__ __forceinline__ unsigned long long pack2(float lo, float hi)
{
    unsigned long long r;
    asm("mov.b64 %0, {%1, %2};" : "=l"(r)
        : "r"(__float_as_uint(lo)), "r"(__float_as_uint(hi)));
    return r;
}
__device__ __forceinline__ void unpack2(unsigned long long v, float& lo, float& hi)
{
    unsigned int a, b;
    asm("mov.b64 {%0, %1}, %2;" : "=r"(a), "=r"(b) : "l"(v));
    lo = __uint_as_float(a); hi = __uint_as_float(b);
}

__global__ void __launch_bounds__(128)
k_transform(const float* __restrict__ Wgc, const float* __restrict__ bgc,
            const float* __restrict__ Wbi, const float* __restrict__ bbi,
            int N, int out_col)
{
    __shared__ __align__(16) float sWgc[EMBD * EMBD];
    __shared__ __align__(16) float sWbi[EMBD * EMBD];
    __shared__ float sB[EMBD];

    for (int t = threadIdx.x; t < EMBD * EMBD; t += blockDim.x) {
        sWgc[t] = Wgc[t];
        sWbi[t] = Wbi[t];
    }
    if (threadIdx.x < EMBD) sB[threadIdx.x] = bgc[threadIdx.x] + bbi[threadIdx.x];
    __syncthreads();

    int n = blockIdx.x * blockDim.x + threadIdx.x;
    if (n >= N) return;

    const float* sp = &g_side[(size_t)n * EMBD];
    const float* ep = &g_ego [(size_t)n * EMBD];

    unsigned long long acc2[32];
    #pragma unroll
    for (int j2 = 0; j2 < 32; j2++) acc2[j2] = pack2(sB[2 * j2], sB[2 * j2 + 1]);

    #pragma unroll 4
    for (int i4 = 0; i4 < 16; i4++) {
        float4 s4 = __ldg(reinterpret_cast<const float4*>(&sp[i4 * 4]));
        float4 e4 = __ldg(reinterpret_cast<const float4*>(&ep[i4 * 4]));
        float ss[4] = {s4.x, s4.y, s4.z, s4.w};
        float pp[4] = {s4.x * e4.x, s4.y * e4.y, s4.z * e4.z, s4.w * e4.w};
        #pragma unroll
        for (int sub = 0; sub < 4; sub++) {
            int i = i4 * 4 + sub;
            unsigned long long s2 = pack2(ss[sub], ss[sub]);
            unsigned long long p2 = pack2(pp[sub], pp[sub]);
            const ulonglong2* wg = reinterpret_cast<const ulonglong2*>(&sWgc[i * EMBD]);
            const ulonglong2* wb = reinterpret_cast<const ulonglong2*>(&sWbi[i * EMBD]);
            #pragma unroll
            for (int q = 0; q < 16; q++) {
                ulonglong2 a = wg[q];
                ulonglong2 b = wb[q];
                FMA2(acc2[q * 2    ], s2, a.x);
                FMA2(acc2[q * 2 + 1], s2, a.y);
                FMA2(acc2[q * 2    ], p2, b.x);
                FMA2(acc2[q * 2 + 1], p2, b.y);
            }
        }
    }

    float acc[EMBD];
    float sumsq = 0.f;
    #pragma unroll
    for (int j2 = 0; j2 < 32; j2++) {
        float lo, hi;
        unpack2(acc2[j2], lo, hi);
        lo = (lo >= 0.f) ? lo : 0.2f * lo;
        hi = (hi >= 0.f) ? hi : 0.2f * hi;
        acc[2 * j2] = lo; acc[2 * j2 + 1] = hi;
        sumsq += lo * lo + hi * hi;
    }
    float inv = 1.0f / fmaxf(sqrtf(sumsq), 1e-12f);

    float* epw = &g_ego [(size_t)n * EMBD];
    float* ap  = &g_alle[(size_t)n * ALLW + out_col];
    #pragma unroll
    for (int j4 = 0; j4 < 16; j4++) {
        float4 v = make_float4(acc[j4*4+0], acc[j4*4+1], acc[j4*4+2], acc[j4*4+3]);
        *reinterpret_cast<float4*>(&epw[j4 * 4]) = v;     // ego (unnormalized)
        v.x *= inv; v.y *= inv; v.z *= inv; v.w *= inv;
        *reinterpret_cast<float4*>(&ap[j4 * 4]) = v;      // normalized slice
    }
}

// ---------------------------------------------------------------------------
// final gather: out = [all_e[users], all_e[n_user+pos], all_e[n_user+neg]]
// Index arrays may be int32 or int64 (JAX x64 ambiguity) -> detect on device.
// ---------------------------------------------------------------------------
__device__ __forceinline__ int detect_is64(const int* w, int count)
{
    int n = (count < 64) ? count : 64;
    int f = 0;
    for (int k = 1; k < 2 * n; k += 2) f |= w[k];
    return (f == 0) ? 1 : 0;
}

__global__ void k_gather(const void* __restrict__ users, const void* __restrict__ pos,
                         const void* __restrict__ neg, float* __restrict__ out,
                         int n_user, int batch)
{
    __shared__ int sIs64[3];
    if (threadIdx.x < 3) {
        const void* a = (threadIdx.x == 0) ? users : (threadIdx.x == 1) ? pos : neg;
        sIs64[threadIdx.x] = detect_is64(reinterpret_cast<const int*>(a), batch);
    }
    __syncthreads();

    int row = blockIdx.x * 4 + (threadIdx.x >> 6);   // 4 rows / 256-thread block
    int c   = threadIdx.x & 63;
    if (row >= 3 * batch) return;
    int grp = row / batch;
    int idx = row - grp * batch;
    const void* a = (grp == 0) ? users : (grp == 1) ? pos : neg;
    long long node;
    if (sIs64[grp]) node = reinterpret_cast<const long long*>(a)[idx];
    else            node = (long long)reinterpret_cast<const int*>(a)[idx];
    if (grp > 0) node += n_user;

    float4 v = *reinterpret_cast<const float4*>(&g_alle[(size_t)node * ALLW + c * 4]);
    *reinterpret_cast<float4*>(&out[(size_t)row * ALLW + c * 4]) = v;
}

// ---------------------------------------------------------------------------
extern "C" void kernel_launch(void* const* d_in, const int* in_sizes, int n_in,
                              void* d_out, int out_size)
{
    const float* user_emb = (const float*)d_in[0];
    const float* item_emb = (const float*)d_in[1];
    const float* W_gc     = (const float*)d_in[2];
    const float* b_gc     = (const float*)d_in[3];
    const float* W_bi     = (const float*)d_in[4];
    const float* b_bi     = (const float*)d_in[5];
    const float* edge_w   = (const float*)d_in[6];
    const int*   edge_src = (const int*)  d_in[7];
    const int*   edge_dst = (const int*)  d_in[8];
    const void*  users    = d_in[9];
    const void*  pos      = d_in[10];
    const void*  neg      = d_in[11];

    int n_user = in_sizes[0] / EMBD;
    int n_item = in_sizes[1] / EMBD;
    int N      = n_user + n_item;
    int layers = in_sizes[2] / (EMBD * EMBD);
    int nE     = in_sizes[6];
    int batch  = in_sizes[9];

    // init (also zeroes deg)
    {
        size_t total = (size_t)N * 16;
        int grid = (int)((total + 255) / 256);
        k_init<<<grid, 256>>>((const float4*)user_emb, (const float4*)item_emb,
                              n_user, N);
    }

    // CSR build (once per call)
    int nblk = (N + 1023) / 1024;
    k_hist<<<(nE + 255) / 256, 256>>>(edge_dst, nE);
    k_scan_blocks<<<nblk, 256>>>(N);
    k_scan_partials<<<1, 256>>>(nblk, nE, N);
    k_scan_write<<<nblk, 256>>>(N);
    k_fill<<<(nE + 255) / 256, 256>>>(edge_src, edge_dst, edge_w, nE);

    // propagation layers
    for (int k = 0; k < layers; k++) {
        {
            size_t threads = (size_t)N * 16;
            int grid = (int)((threads + 255) / 256);
            k_aggregate<<<grid, 256>>>(N);
        }
        {
            int grid = (N + 127) / 128;
            k_transform<<<grid, 128>>>(W_gc + (size_t)k * EMBD * EMBD,
                                       b_gc + (size_t)k * EMBD,
                                       W_bi + (size_t)k * EMBD * EMBD,
                                       b_bi + (size_t)k * EMBD,
                                       N, EMBD * (k + 1));
        }
    }

    // final gather
    {
        int rows = 3 * batch;
        int grid = (rows + 3) / 4;
        k_gather<<<grid, 256>>>(users, pos, neg, (float*)d_out, n_user, batch);
    }
}

// round 10
// speedup vs baseline: 2.1177x; 1.1575x over previous
#include <cuda_runtime.h>
#include <cuda_fp16.h>
#include <cstdint>

// Problem-size constants (sized for this dataset)
#define MAX_N      150016
#define MAX_E      4194304
#define EMBD       64
#define ALLW       256   // 4 * EMB concatenated width

// -------- scratch (device globals: no allocations allowed) ----------------
__device__ float  g_side [(size_t)MAX_N * EMBD];    // 38.4 MB
__device__ float  g_ego  [(size_t)MAX_N * EMBD];    // 38.4 MB (fp32 master)
__device__ __half g_ego16[(size_t)MAX_N * EMBD];    // 19.2 MB (gather mirror)
__device__ float  g_alle [(size_t)MAX_N * ALLW];    // 153.6 MB
__device__ int    g_deg [MAX_N];
__device__ int    g_row [MAX_N + 1];
__device__ int    g_cur [MAX_N];
__device__ int    g_partial[256];
__device__ int    g_poff  [256];
__device__ int2   g_edge[MAX_E];                    // (src, w-bits) 32 MB

// ---------------------------------------------------------------------------
// init: ego/ego16 = concat(user_emb,item_emb); all_e[:,0:64] = ego; deg = 0
// one thread per float4 chunk of a row (16 chunks/row)
// ---------------------------------------------------------------------------
__global__ void k_init(const float4* __restrict__ ue, const float4* __restrict__ ie,
                       int n_user, int N)
{
    size_t t = (size_t)blockIdx.x * blockDim.x + threadIdx.x;
    size_t total = (size_t)N * 16;
    if (t >= total) return;
    int row = (int)(t >> 4);
    int c   = (int)(t & 15);
    float4 v = (row < n_user) ? ue[(size_t)row * 16 + c]
                              : ie[(size_t)(row - n_user) * 16 + c];
    reinterpret_cast<float4*>(g_ego )[t] = v;
    reinterpret_cast<float4*>(g_alle)[(size_t)row * 64 + c] = v;  // cols 0..63
    __half2 h0 = __floats2half2_rn(v.x, v.y);
    __half2 h1 = __floats2half2_rn(v.z, v.w);
    uint2 hp = make_uint2(*reinterpret_cast<unsigned*>(&h0),
                          *reinterpret_cast<unsigned*>(&h1));
    reinterpret_cast<uint2*>(g_ego16)[t] = hp;
    if (c == 0) g_deg[row] = 0;
}

// ---------------------------------------------------------------------------
// CSR build: histogram -> block sums -> scan partials -> write offsets -> fill
// ---------------------------------------------------------------------------
__global__ void k_hist(const int* __restrict__ dst, int nE)
{
    int e = blockIdx.x * blockDim.x + threadIdx.x;
    if (e < nE) atomicAdd(&g_deg[dst[e]], 1);
}

__global__ void k_scan_blocks(int N)
{
    __shared__ int s[256];
    int tid  = threadIdx.x;
    int base = blockIdx.x * 1024 + tid * 4;
    int ts = 0;
    #pragma unroll
    for (int k = 0; k < 4; k++)
        if (base + k < N) ts += g_deg[base + k];
    s[tid] = ts;
    __syncthreads();
    for (int off = 128; off > 0; off >>= 1) {
        if (tid < off) s[tid] += s[tid + off];
        __syncthreads();
    }
    if (tid == 0) g_partial[blockIdx.x] = s[0];
}

__global__ void k_scan_partials(int nblk, int nE, int N)
{
    __shared__ int s[256];
    int tid = threadIdx.x;
    int v = (tid < nblk) ? g_partial[tid] : 0;
    s[tid] = v;
    __syncthreads();
    for (int off = 1; off < 256; off <<= 1) {
        int t = (tid >= off) ? s[tid - off] : 0;
        __syncthreads();
        s[tid] += t;
        __syncthreads();
    }
    g_poff[tid] = s[tid] - v;   // exclusive
    if (tid == 0) g_row[N] = nE;
}

__global__ void k_scan_write(int N)
{
    __shared__ int s[256];
    int tid  = threadIdx.x;
    int base = blockIdx.x * 1024 + tid * 4;
    int v[4]; int ts = 0;
    #pragma unroll
    for (int k = 0; k < 4; k++) {
        v[k] = (base + k < N) ? g_deg[base + k] : 0;
        ts += v[k];
    }
    s[tid] = ts;
    __syncthreads();
    for (int off = 1; off < 256; off <<= 1) {
        int t = (tid >= off) ? s[tid - off] : 0;
        __syncthreads();
        s[tid] += t;
        __syncthreads();
    }
    int excl = s[tid] - ts + g_poff[blockIdx.x];
    #pragma unroll
    for (int k = 0; k < 4; k++) {
        if (base + k < N) {
            g_row[base + k] = excl;
            g_cur[base + k] = excl;
            excl += v[k];
        }
    }
}

__global__ void k_fill(const int* __restrict__ src, const int* __restrict__ dst,
                       const float* __restrict__ w, int nE)
{
    int e = blockIdx.x * blockDim.x + threadIdx.x;
    if (e >= nE) return;
    int d   = dst[e];
    int pos = atomicAdd(&g_cur[d], 1);
    g_edge[pos] = make_int2(src[e], __float_as_int(w[e]));
}

// ---------------------------------------------------------------------------
// aggregate: side[n] = sum_{e in CSR row n} w_e * ego16[src_e]  (fp32 accum)
// 16 threads per node, each owns one 4-element chunk (8B fp16 load).
// ---------------------------------------------------------------------------
__global__ void __launch_bounds__(256)
k_aggregate(int N)
{
    size_t t = (size_t)blockIdx.x * blockDim.x + threadIdx.x;
    int node = (int)(t >> 4);
    int c    = (int)(t & 15);
    if (node >= N) return;
    int beg = g_row[node];
    int end = g_row[node + 1];
    const uint2* ebase = reinterpret_cast<const uint2*>(g_ego16);
    float4 acc = make_float4(0.f, 0.f, 0.f, 0.f);
    #pragma unroll 4
    for (int e = beg; e < end; e++) {
        int2  sw = g_edge[e];
        float w  = __int_as_float(sw.y);
        uint2 r  = __ldg(&ebase[(size_t)sw.x * 16 + c]);
        __half2 h0 = *reinterpret_cast<__half2*>(&r.x);
        __half2 h1 = *reinterpret_cast<__half2*>(&r.y);
        float2 f0 = __half22float2(h0);
        float2 f1 = __half22float2(h1);
        acc.x += w * f0.x; acc.y += w * f0.y;
        acc.z += w * f1.x; acc.w += w * f1.y;
    }
    *reinterpret_cast<float4*>(&g_side[(size_t)node * EMBD + c * 4]) = acc;
}

// ---------------------------------------------------------------------------
// transform: fused dual-GEMM + bias + leaky_relu + row-norm, packed f32x2 FMA.
// TWO nodes per thread: weight LDS amortized over both.
//   sum_e = side @ Wgc + bgc ; bi_e = (ego*side) @ Wbi + bbi
//   ego   = leaky_relu(sum_e + bi_e, 0.2)   (in-place, unnormalized; + fp16 mirror)
//   all_e[:, out_col : +64] = ego / max(||ego||, 1e-12)
// ---------------------------------------------------------------------------
#define FMA2(d, a, b) asm("fma.rn.f32x2 %0, %1, %2, %0;" : "+l"(d) : "l"(a), "l"(b))

__device__ __forceinline__ unsigned long long pack2(float lo, float hi)
{
    unsigned long long r;
    asm("mov.b64 %0, {%1, %2};" : "=l"(r)
        : "r"(__float_as_uint(lo)), "r"(__float_as_uint(hi)));
    return r;
}
__device__ __forceinline__ void unpack2(unsigned long long v, float& lo, float& hi)
{
    unsigned int a, b;
    asm("mov.b64 {%0, %1}, %2;" : "=r"(a), "=r"(b) : "l"(v));
    lo = __uint_as_float(a); hi = __uint_as_float(b);
}

__device__ __forceinline__ void epilogue_node(unsigned long long* acc2, int n, int out_col)
{
    float acc[EMBD];
    float sumsq = 0.f;
    #pragma unroll
    for (int j2 = 0; j2 < 32; j2++) {
        float lo, hi;
        unpack2(acc2[j2], lo, hi);
        lo = (lo >= 0.f) ? lo : 0.2f * lo;
        hi = (hi >= 0.f) ? hi : 0.2f * hi;
        acc[2 * j2] = lo; acc[2 * j2 + 1] = hi;
        sumsq += lo * lo + hi * hi;
    }
    float inv = 1.0f / fmaxf(sqrtf(sumsq), 1e-12f);

    float* epw = &g_ego [(size_t)n * EMBD];
    float* ap  = &g_alle[(size_t)n * ALLW + out_col];
    uint2* e16 = reinterpret_cast<uint2*>(&g_ego16[(size_t)n * EMBD]);
    #pragma unroll
    for (int j4 = 0; j4 < 16; j4++) {
        float4 v = make_float4(acc[j4*4+0], acc[j4*4+1], acc[j4*4+2], acc[j4*4+3]);
        *reinterpret_cast<float4*>(&epw[j4 * 4]) = v;     // ego fp32 (unnormalized)
        __half2 h0 = __floats2half2_rn(v.x, v.y);
        __half2 h1 = __floats2half2_rn(v.z, v.w);
        e16[j4] = make_uint2(*reinterpret_cast<unsigned*>(&h0),
                             *reinterpret_cast<unsigned*>(&h1));
        v.x *= inv; v.y *= inv; v.z *= inv; v.w *= inv;
        *reinterpret_cast<float4*>(&ap[j4 * 4]) = v;      // normalized slice
    }
}

__global__ void __launch_bounds__(128, 1)
k_transform(const float* __restrict__ Wgc, const float* __restrict__ bgc,
            const float* __restrict__ Wbi, const float* __restrict__ bbi,
            int N, int out_col)
{
    __shared__ __align__(16) float sWgc[EMBD * EMBD];
    __shared__ __align__(16) float sWbi[EMBD * EMBD];
    __shared__ float sB[EMBD];

    for (int t = threadIdx.x; t < EMBD * EMBD; t += blockDim.x) {
        sWgc[t] = Wgc[t];
        sWbi[t] = Wbi[t];
    }
    if (threadIdx.x < EMBD) sB[threadIdx.x] = bgc[threadIdx.x] + bbi[threadIdx.x];
    __syncthreads();

    int n0 = (blockIdx.x * blockDim.x + threadIdx.x) * 2;
    if (n0 >= N) return;
    int n1 = (n0 + 1 < N) ? n0 + 1 : n0;   // clamp: duplicate work, same result

    const float* spA = &g_side[(size_t)n0 * EMBD];
    const float* epA = &g_ego [(size_t)n0 * EMBD];
    const float* spB = &g_side[(size_t)n1 * EMBD];
    const float* epB = &g_ego [(size_t)n1 * EMBD];

    unsigned long long accA[32], accB[32];
    #pragma unroll
    for (int j2 = 0; j2 < 32; j2++) {
        unsigned long long b2 = pack2(sB[2 * j2], sB[2 * j2 + 1]);
        accA[j2] = b2; accB[j2] = b2;
    }

    #pragma unroll 2
    for (int i4 = 0; i4 < 16; i4++) {
        float4 sA = __ldg(reinterpret_cast<const float4*>(&spA[i4 * 4]));
        float4 eA = __ldg(reinterpret_cast<const float4*>(&epA[i4 * 4]));
        float4 sBv= __ldg(reinterpret_cast<const float4*>(&spB[i4 * 4]));
        float4 eB = __ldg(reinterpret_cast<const float4*>(&epB[i4 * 4]));
        float ssA[4] = {sA.x, sA.y, sA.z, sA.w};
        float ppA[4] = {sA.x * eA.x, sA.y * eA.y, sA.z * eA.z, sA.w * eA.w};
        float ssB[4] = {sBv.x, sBv.y, sBv.z, sBv.w};
        float ppB[4] = {sBv.x * eB.x, sBv.y * eB.y, sBv.z * eB.z, sBv.w * eB.w};
        #pragma unroll
        for (int sub = 0; sub < 4; sub++) {
            int i = i4 * 4 + sub;
            unsigned long long s2A = pack2(ssA[sub], ssA[sub]);
            unsigned long long p2A = pack2(ppA[sub], ppA[sub]);
            unsigned long long s2B = pack2(ssB[sub], ssB[sub]);
            unsigned long long p2B = pack2(ppB[sub], ppB[sub]);
            const ulonglong2* wg = reinterpret_cast<const ulonglong2*>(&sWgc[i * EMBD]);
            const ulonglong2* wb = reinterpret_cast<const ulonglong2*>(&sWbi[i * EMBD]);
            #pragma unroll
            for (int q = 0; q < 16; q++) {
                ulonglong2 a = wg[q];
                ulonglong2 b = wb[q];
                FMA2(accA[q * 2    ], s2A, a.x);
                FMA2(accA[q * 2 + 1], s2A, a.y);
                FMA2(accA[q * 2    ], p2A, b.x);
                FMA2(accA[q * 2 + 1], p2A, b.y);
                FMA2(accB[q * 2    ], s2B, a.x);
                FMA2(accB[q * 2 + 1], s2B, a.y);
                FMA2(accB[q * 2    ], p2B, b.x);
                FMA2(accB[q * 2 + 1], p2B, b.y);
            }
        }
    }

    epilogue_node(accA, n0, out_col);
    if (n1 != n0) epilogue_node(accB, n1, out_col);
}

// ---------------------------------------------------------------------------
// final gather: out = [all_e[users], all_e[n_user+pos], all_e[n_user+neg]]
// Index arrays may be int32 or int64 (JAX x64 ambiguity) -> detect on device.
// ---------------------------------------------------------------------------
__device__ __forceinline__ int detect_is64(const int* w, int count)
{
    int n = (count < 64) ? count : 64;
    int f = 0;
    for (int k = 1; k < 2 * n; k += 2) f |= w[k];
    return (f == 0) ? 1 : 0;
}

__global__ void k_gather(const void* __restrict__ users, const void* __restrict__ pos,
                         const void* __restrict__ neg, float* __restrict__ out,
                         int n_user, int batch)
{
    __shared__ int sIs64[3];
    if (threadIdx.x < 3) {
        const void* a = (threadIdx.x == 0) ? users : (threadIdx.x == 1) ? pos : neg;
        sIs64[threadIdx.x] = detect_is64(reinterpret_cast<const int*>(a), batch);
    }
    __syncthreads();

    int row = blockIdx.x * 4 + (threadIdx.x >> 6);   // 4 rows / 256-thread block
    int c   = threadIdx.x & 63;
    if (row >= 3 * batch) return;
    int grp = row / batch;
    int idx = row - grp * batch;
    const void* a = (grp == 0) ? users : (grp == 1) ? pos : neg;
    long long node;
    if (sIs64[grp]) node = reinterpret_cast<const long long*>(a)[idx];
    else            node = (long long)reinterpret_cast<const int*>(a)[idx];
    if (grp > 0) node += n_user;

    float4 v = *reinterpret_cast<const float4*>(&g_alle[(size_t)node * ALLW + c * 4]);
    *reinterpret_cast<float4*>(&out[(size_t)row * ALLW + c * 4]) = v;
}

// ---------------------------------------------------------------------------
extern "C" void kernel_launch(void* const* d_in, const int* in_sizes, int n_in,
                              void* d_out, int out_size)
{
    const float* user_emb = (const float*)d_in[0];
    const float* item_emb = (const float*)d_in[1];
    const float* W_gc     = (const float*)d_in[2];
    const float* b_gc     = (const float*)d_in[3];
    const float* W_bi     = (const float*)d_in[4];
    const float* b_bi     = (const float*)d_in[5];
    const float* edge_w   = (const float*)d_in[6];
    const int*   edge_src = (const int*)  d_in[7];
    const int*   edge_dst = (const int*)  d_in[8];
    const void*  users    = d_in[9];
    const void*  pos      = d_in[10];
    const void*  neg      = d_in[11];

    int n_user = in_sizes[0] / EMBD;
    int n_item = in_sizes[1] / EMBD;
    int N      = n_user + n_item;
    int layers = in_sizes[2] / (EMBD * EMBD);
    int nE     = in_sizes[6];
    int batch  = in_sizes[9];

    // init (also zeroes deg, writes fp16 mirror)
    {
        size_t total = (size_t)N * 16;
        int grid = (int)((total + 255) / 256);
        k_init<<<grid, 256>>>((const float4*)user_emb, (const float4*)item_emb,
                              n_user, N);
    }

    // CSR build (once per call)
    int nblk = (N + 1023) / 1024;
    k_hist<<<(nE + 255) / 256, 256>>>(edge_dst, nE);
    k_scan_blocks<<<nblk, 256>>>(N);
    k_scan_partials<<<1, 256>>>(nblk, nE, N);
    k_scan_write<<<nblk, 256>>>(N);
    k_fill<<<(nE + 255) / 256, 256>>>(edge_src, edge_dst, edge_w, nE);

    // propagation layers
    for (int k = 0; k < layers; k++) {
        {
            size_t threads = (size_t)N * 16;
            int grid = (int)((threads + 255) / 256);
            k_aggregate<<<grid, 256>>>(N);
        }
        {
            int pairs = (N + 1) / 2;
            int grid  = (pairs + 127) / 128;
            k_transform<<<grid, 128>>>(W_gc + (size_t)k * EMBD * EMBD,
                                       b_gc + (size_t)k * EMBD,
                                       W_bi + (size_t)k * EMBD * EMBD,
                                       b_bi + (size_t)k * EMBD,
                                       N, EMBD * (k + 1));
        }
    }

    // final gather
    {
        int rows = 3 * batch;
        int grid = (rows + 3) / 4;
        k_gather<<<grid, 256>>>(users, pos, neg, (float*)d_out, n_user, batch);
    }
}

// round 11
// speedup vs baseline: 2.1504x; 1.0155x over previous
#include <cuda_runtime.h>
#include <cuda_fp16.h>
#include <cstdint>

// Problem-size constants (sized for this dataset)
#define MAX_N      150016
#define MAX_E      4194304
#define EMBD       64
#define ALLW       256   // 4 * EMB concatenated width

// -------- scratch (device globals: no allocations allowed) ----------------
__device__ float  g_side [(size_t)MAX_N * EMBD];    // 38.4 MB
__device__ __half g_ego16[(size_t)MAX_N * EMBD];    // 19.2 MB (recurrence state)
__device__ float  g_alle [(size_t)MAX_N * ALLW];    // 153.6 MB
__device__ int    g_deg [MAX_N];
__device__ int    g_row [MAX_N + 1];
__device__ int    g_cur [MAX_N];
__device__ int    g_partial[256];
__device__ int2   g_edge[MAX_E];                    // (src, w-bits) 32 MB

// ---------------------------------------------------------------------------
// init: ego16 = concat(user_emb,item_emb); all_e[:,0:64] = same (fp32); deg = 0
// one thread per float4 chunk of a row (16 chunks/row)
// ---------------------------------------------------------------------------
__global__ void k_init(const float4* __restrict__ ue, const float4* __restrict__ ie,
                       int n_user, int N)
{
    size_t t = (size_t)blockIdx.x * blockDim.x + threadIdx.x;
    size_t total = (size_t)N * 16;
    if (t >= total) return;
    int row = (int)(t >> 4);
    int c   = (int)(t & 15);
    float4 v = (row < n_user) ? ue[(size_t)row * 16 + c]
                              : ie[(size_t)(row - n_user) * 16 + c];
    reinterpret_cast<float4*>(g_alle)[(size_t)row * 64 + c] = v;  // cols 0..63 (fp32 exact)
    __half2 h0 = __floats2half2_rn(v.x, v.y);
    __half2 h1 = __floats2half2_rn(v.z, v.w);
    uint2 hp = make_uint2(*reinterpret_cast<unsigned*>(&h0),
                          *reinterpret_cast<unsigned*>(&h1));
    reinterpret_cast<uint2*>(g_ego16)[t] = hp;
    if (c == 0) g_deg[row] = 0;
}

// ---------------------------------------------------------------------------
// CSR build: histogram -> block sums -> (partial-scan + offsets fused) -> fill
// ---------------------------------------------------------------------------
__global__ void k_hist(const int* __restrict__ dst, int nE)
{
    int e = blockIdx.x * blockDim.x + threadIdx.x;
    if (e < nE) atomicAdd(&g_deg[dst[e]], 1);
}

// block of 256 threads covers 1024 elements; writes per-block sum
__global__ void k_scan_blocks(int N)
{
    __shared__ int s[256];
    int tid  = threadIdx.x;
    int base = blockIdx.x * 1024 + tid * 4;
    int ts = 0;
    #pragma unroll
    for (int k = 0; k < 4; k++)
        if (base + k < N) ts += g_deg[base + k];
    s[tid] = ts;
    __syncthreads();
    for (int off = 128; off > 0; off >>= 1) {
        if (tid < off) s[tid] += s[tid + off];
        __syncthreads();
    }
    if (tid == 0) g_partial[blockIdx.x] = s[0];
}

// fused: every block scans the (<=256) per-block partials in smem, takes its
// exclusive offset, then scans its own 1024 elements and writes row/cur.
__global__ void k_scan_write(int nblk, int nE, int N)
{
    __shared__ int ps[256];
    __shared__ int s[256];
    int tid = threadIdx.x;

    ps[tid] = (tid < nblk) ? g_partial[tid] : 0;
    __syncthreads();
    for (int off = 1; off < 256; off <<= 1) {
        int t = (tid >= off) ? ps[tid - off] : 0;
        __syncthreads();
        ps[tid] += t;
        __syncthreads();
    }
    int block_off = (blockIdx.x > 0) ? ps[blockIdx.x - 1] : 0;  // exclusive

    int base = blockIdx.x * 1024 + tid * 4;
    int v[4]; int ts = 0;
    #pragma unroll
    for (int k = 0; k < 4; k++) {
        v[k] = (base + k < N) ? g_deg[base + k] : 0;
        ts += v[k];
    }
    s[tid] = ts;
    __syncthreads();
    for (int off = 1; off < 256; off <<= 1) {
        int t = (tid >= off) ? s[tid - off] : 0;
        __syncthreads();
        s[tid] += t;
        __syncthreads();
    }
    int excl = s[tid] - ts + block_off;
    #pragma unroll
    for (int k = 0; k < 4; k++) {
        if (base + k < N) {
            g_row[base + k] = excl;
            g_cur[base + k] = excl;
            excl += v[k];
        }
    }
    if (blockIdx.x == 0 && tid == 0) g_row[N] = nE;
}

__global__ void k_fill(const int* __restrict__ src, const int* __restrict__ dst,
                       const float* __restrict__ w, int nE)
{
    int e = blockIdx.x * blockDim.x + threadIdx.x;
    if (e >= nE) return;
    int d   = dst[e];
    int pos = atomicAdd(&g_cur[d], 1);
    g_edge[pos] = make_int2(src[e], __float_as_int(w[e]));
}

// ---------------------------------------------------------------------------
// aggregate: side[n] = sum_{e in CSR row n} w_e * ego16[src_e]  (fp32 accum)
// ONE WARP per node: 2 edges per iteration (halves trip count, doubles MLP),
// lanes [0..15] edge e, [16..31] edge e+1; shfl_xor(16) reduce; no atomics.
// ---------------------------------------------------------------------------
__global__ void __launch_bounds__(256)
k_aggregate(int N)
{
    int node = (int)(((size_t)blockIdx.x * blockDim.x + threadIdx.x) >> 5);
    if (node >= N) return;
    int lane = threadIdx.x & 31;
    int half = lane >> 4;
    int c    = lane & 15;

    int beg = g_row[node];
    int end = g_row[node + 1];
    const uint2* ebase = reinterpret_cast<const uint2*>(g_ego16);

    float4 acc = make_float4(0.f, 0.f, 0.f, 0.f);
    #pragma unroll 4
    for (int e = beg + half; e < end; e += 2) {
        int2  sw = g_edge[e];
        float w  = __int_as_float(sw.y);
        uint2 r  = __ldg(&ebase[(size_t)sw.x * 16 + c]);
        __half2 h0 = *reinterpret_cast<__half2*>(&r.x);
        __half2 h1 = *reinterpret_cast<__half2*>(&r.y);
        float2 f0 = __half22float2(h0);
        float2 f1 = __half22float2(h1);
        acc.x += w * f0.x; acc.y += w * f0.y;
        acc.z += w * f1.x; acc.w += w * f1.y;
    }
    // combine the two edge-halves (chunk c in lane l pairs with lane l^16)
    acc.x += __shfl_xor_sync(0xFFFFFFFFu, acc.x, 16);
    acc.y += __shfl_xor_sync(0xFFFFFFFFu, acc.y, 16);
    acc.z += __shfl_xor_sync(0xFFFFFFFFu, acc.z, 16);
    acc.w += __shfl_xor_sync(0xFFFFFFFFu, acc.w, 16);
    if (half == 0)
        *reinterpret_cast<float4*>(&g_side[(size_t)node * EMBD + c * 4]) = acc;
}

// ---------------------------------------------------------------------------
// transform: fused dual-GEMM + bias + leaky_relu + row-norm, packed f32x2 FMA.
// TWO nodes per thread (weight LDS amortized). ego read from fp16 mirror.
//   sum_e = side @ Wgc + bgc ; bi_e = (ego*side) @ Wbi + bbi
//   new ego (fp16 mirror) = leaky_relu(sum_e + bi_e, 0.2)
//   all_e[:, out_col : +64] = new_ego / max(||new_ego||, 1e-12)   (fp32)
// ---------------------------------------------------------------------------
#define FMA2(d, a, b) asm("fma.rn.f32x2 %0, %1, %2, %0;" : "+l"(d) : "l"(a), "l"(b))

__device__ __forceinline__ unsigned long long pack2(float lo, float hi)
{
    unsigned long long r;
    asm("mov.b64 %0, {%1, %2};" : "=l"(r)
        : "r"(__float_as_uint(lo)), "r"(__float_as_uint(hi)));
    return r;
}
__device__ __forceinline__ void unpack2(unsigned long long v, float& lo, float& hi)
{
    unsigned int a, b;
    asm("mov.b64 {%0, %1}, %2;" : "=r"(a), "=r"(b) : "l"(v));
    lo = __uint_as_float(a); hi = __uint_as_float(b);
}

__device__ __forceinline__ void epilogue_node(unsigned long long* acc2, int n, int out_col)
{
    // leaky-relu in place (packed) + sum of squares
    float sumsq = 0.f;
    #pragma unroll
    for (int j2 = 0; j2 < 32; j2++) {
        float lo, hi;
        unpack2(acc2[j2], lo, hi);
        lo = (lo >= 0.f) ? lo : 0.2f * lo;
        hi = (hi >= 0.f) ? hi : 0.2f * hi;
        acc2[j2] = pack2(lo, hi);
        sumsq += lo * lo + hi * hi;
    }
    float inv = 1.0f / fmaxf(sqrtf(sumsq), 1e-12f);

    float* ap  = &g_alle[(size_t)n * ALLW + out_col];
    uint2* e16 = reinterpret_cast<uint2*>(&g_ego16[(size_t)n * EMBD]);
    #pragma unroll
    for (int j4 = 0; j4 < 16; j4++) {
        float a0, a1, a2, a3;
        unpack2(acc2[2 * j4    ], a0, a1);
        unpack2(acc2[2 * j4 + 1], a2, a3);
        __half2 h0 = __floats2half2_rn(a0, a1);
        __half2 h1 = __floats2half2_rn(a2, a3);
        e16[j4] = make_uint2(*reinterpret_cast<unsigned*>(&h0),
                             *reinterpret_cast<unsigned*>(&h1));
        float4 v = make_float4(a0 * inv, a1 * inv, a2 * inv, a3 * inv);
        *reinterpret_cast<float4*>(&ap[j4 * 4]) = v;      // normalized slice (fp32)
    }
}

__global__ void __launch_bounds__(128)
k_transform(const float* __restrict__ Wgc, const float* __restrict__ bgc,
            const float* __restrict__ Wbi, const float* __restrict__ bbi,
            int N, int out_col)
{
    __shared__ __align__(16) float sWgc[EMBD * EMBD];
    __shared__ __align__(16) float sWbi[EMBD * EMBD];
    __shared__ float sB[EMBD];

    for (int t = threadIdx.x; t < EMBD * EMBD; t += blockDim.x) {
        sWgc[t] = Wgc[t];
        sWbi[t] = Wbi[t];
    }
    if (threadIdx.x < EMBD) sB[threadIdx.x] = bgc[threadIdx.x] + bbi[threadIdx.x];
    __syncthreads();

    int n0 = (blockIdx.x * blockDim.x + threadIdx.x) * 2;
    if (n0 >= N) return;
    int n1 = (n0 + 1 < N) ? n0 + 1 : n0;   // clamp: duplicate work, same result

    const float* spA = &g_side[(size_t)n0 * EMBD];
    const float* spB = &g_side[(size_t)n1 * EMBD];
    const uint2* e16 = reinterpret_cast<const uint2*>(g_ego16);

    unsigned long long accA[32], accB[32];
    #pragma unroll
    for (int j2 = 0; j2 < 32; j2++) {
        unsigned long long b2 = pack2(sB[2 * j2], sB[2 * j2 + 1]);
        accA[j2] = b2; accB[j2] = b2;
    }

    #pragma unroll 2
    for (int i4 = 0; i4 < 16; i4++) {
        float4 sA  = __ldg(reinterpret_cast<const float4*>(&spA[i4 * 4]));
        float4 sBv = __ldg(reinterpret_cast<const float4*>(&spB[i4 * 4]));
        uint2  rA  = __ldg(&e16[(size_t)n0 * 16 + i4]);
        uint2  rB  = __ldg(&e16[(size_t)n1 * 16 + i4]);
        float2 eA0 = __half22float2(*reinterpret_cast<__half2*>(&rA.x));
        float2 eA1 = __half22float2(*reinterpret_cast<__half2*>(&rA.y));
        float2 eB0 = __half22float2(*reinterpret_cast<__half2*>(&rB.x));
        float2 eB1 = __half22float2(*reinterpret_cast<__half2*>(&rB.y));
        float ssA[4] = {sA.x, sA.y, sA.z, sA.w};
        float ppA[4] = {sA.x * eA0.x, sA.y * eA0.y, sA.z * eA1.x, sA.w * eA1.y};
        float ssB[4] = {sBv.x, sBv.y, sBv.z, sBv.w};
        float ppB[4] = {sBv.x * eB0.x, sBv.y * eB0.y, sBv.z * eB1.x, sBv.w * eB1.y};
        #pragma unroll
        for (int sub = 0; sub < 4; sub++) {
            int i = i4 * 4 + sub;
            unsigned long long s2A = pack2(ssA[sub], ssA[sub]);
            unsigned long long p2A = pack2(ppA[sub], ppA[sub]);
            unsigned long long s2B = pack2(ssB[sub], ssB[sub]);
            unsigned long long p2B = pack2(ppB[sub], ppB[sub]);
            const ulonglong2* wg = reinterpret_cast<const ulonglong2*>(&sWgc[i * EMBD]);
            const ulonglong2* wb = reinterpret_cast<const ulonglong2*>(&sWbi[i * EMBD]);
            #pragma unroll
            for (int q = 0; q < 16; q++) {
                ulonglong2 a = wg[q];
                ulonglong2 b = wb[q];
                FMA2(accA[q * 2    ], s2A, a.x);
                FMA2(accA[q * 2 + 1], s2A, a.y);
                FMA2(accA[q * 2    ], p2A, b.x);
                FMA2(accA[q * 2 + 1], p2A, b.y);
                FMA2(accB[q * 2    ], s2B, a.x);
                FMA2(accB[q * 2 + 1], s2B, a.y);
                FMA2(accB[q * 2    ], p2B, b.x);
                FMA2(accB[q * 2 + 1], p2B, b.y);
            }
        }
    }

    epilogue_node(accA, n0, out_col);
    if (n1 != n0) epilogue_node(accB, n1, out_col);
}

// ---------------------------------------------------------------------------
// final gather: out = [all_e[users], all_e[n_user+pos], all_e[n_user+neg]]
// Index arrays may be int32 or int64 (JAX x64 ambiguity) -> detect on device.
// ---------------------------------------------------------------------------
__device__ __forceinline__ int detect_is64(const int* w, int count)
{
    int n = (count < 64) ? count : 64;
    int f = 0;
    for (int k = 1; k < 2 * n; k += 2) f |= w[k];
    return (f == 0) ? 1 : 0;
}

__global__ void k_gather(const void* __restrict__ users, const void* __restrict__ pos,
                         const void* __restrict__ neg, float* __restrict__ out,
                         int n_user, int batch)
{
    __shared__ int sIs64[3];
    if (threadIdx.x < 3) {
        const void* a = (threadIdx.x == 0) ? users : (threadIdx.x == 1) ? pos : neg;
        sIs64[threadIdx.x] = detect_is64(reinterpret_cast<const int*>(a), batch);
    }
    __syncthreads();

    int row = blockIdx.x * 4 + (threadIdx.x >> 6);   // 4 rows / 256-thread block
    int c   = threadIdx.x & 63;
    if (row >= 3 * batch) return;
    int grp = row / batch;
    int idx = row - grp * batch;
    const void* a = (grp == 0) ? users : (grp == 1) ? pos : neg;
    long long node;
    if (sIs64[grp]) node = reinterpret_cast<const long long*>(a)[idx];
    else            node = (long long)reinterpret_cast<const int*>(a)[idx];
    if (grp > 0) node += n_user;

    float4 v = *reinterpret_cast<const float4*>(&g_alle[(size_t)node * ALLW + c * 4]);
    *reinterpret_cast<float4*>(&out[(size_t)row * ALLW + c * 4]) = v;
}

// ---------------------------------------------------------------------------
extern "C" void kernel_launch(void* const* d_in, const int* in_sizes, int n_in,
                              void* d_out, int out_size)
{
    const float* user_emb = (const float*)d_in[0];
    const float* item_emb = (const float*)d_in[1];
    const float* W_gc     = (const float*)d_in[2];
    const float* b_gc     = (const float*)d_in[3];
    const float* W_bi     = (const float*)d_in[4];
    const float* b_bi     = (const float*)d_in[5];
    const float* edge_w   = (const float*)d_in[6];
    const int*   edge_src = (const int*)  d_in[7];
    const int*   edge_dst = (const int*)  d_in[8];
    const void*  users    = d_in[9];
    const void*  pos      = d_in[10];
    const void*  neg      = d_in[11];

    int n_user = in_sizes[0] / EMBD;
    int n_item = in_sizes[1] / EMBD;
    int N      = n_user + n_item;
    int layers = in_sizes[2] / (EMBD * EMBD);
    int nE     = in_sizes[6];
    int batch  = in_sizes[9];

    // launch 0: init (writes ego16 + alle[:,0:64], zeroes deg)
    {
        size_t total = (size_t)N * 16;
        int grid = (int)((total + 255) / 256);
        k_init<<<grid, 256>>>((const float4*)user_emb, (const float4*)item_emb,
                              n_user, N);
    }

    // CSR build (launches 1..4)
    int nblk = (N + 1023) / 1024;
    k_hist<<<(nE + 255) / 256, 256>>>(edge_dst, nE);
    k_scan_blocks<<<nblk, 256>>>(N);
    k_scan_write<<<nblk, 256>>>(nblk, nE, N);
    k_fill<<<(nE + 255) / 256, 256>>>(edge_src, edge_dst, edge_w, nE);

    // propagation layers (launch 5 = first k_aggregate -> ncu -s 5 target)
    for (int k = 0; k < layers; k++) {
        {
            size_t threads = (size_t)N * 32;
            int grid = (int)((threads + 255) / 256);
            k_aggregate<<<grid, 256>>>(N);
        }
        {
            int pairs = (N + 1) / 2;
            int grid  = (pairs + 127) / 128;
            k_transform<<<grid, 128>>>(W_gc + (size_t)k * EMBD * EMBD,
                                       b_gc + (size_t)k * EMBD,
                                       W_bi + (size_t)k * EMBD * EMBD,
                                       b_bi + (size_t)k * EMBD,
                                       N, EMBD * (k + 1));
        }
    }

    // final gather
    {
        int rows = 3 * batch;
        int grid = (rows + 3) / 4;
        k_gather<<<grid, 256>>>(users, pos, neg, (float*)d_out, n_user, batch);
    }
}